// round 13
// baseline (speedup 1.0000x reference)
#include <cuda_runtime.h>
#include <cuda_bf16.h>
#include <math.h>
#include <stdint.h>

#define V  50257
#define H  1024
#define L  2048
#define ML 2048
#define NRED 52

// ---------------- scratch (device globals; no allocations allowed) ----------------
__device__ float g_al2[2 * ML];      // attn logit half-dots (plain stores, no bias)
__device__ float g_attn_applied[H];
__device__ float g_rnn_in[H];
__device__ float g_gi2[2][3 * H];    // gi half-dots (plain stores, no bias)
__device__ float g_gh[3 * H];
__device__ float g_hnew[H];
__device__ float g_score_g[V];
__device__ float g_score_c[L];
__device__ float g_bmax[NRED];
__device__ float g_bsum[NRED];
__device__ float g_smax;
__device__ float g_sinv;

// ---------------- helpers ----------------
__device__ __forceinline__ float block_reduce_max(float v, float* sred) {
    #pragma unroll
    for (int o = 16; o; o >>= 1) v = fmaxf(v, __shfl_xor_sync(0xffffffffu, v, o));
    int w = threadIdx.x >> 5;
    if ((threadIdx.x & 31) == 0) sred[w] = v;
    __syncthreads();
    int nw = (blockDim.x + 31) >> 5;
    if (threadIdx.x < 32) {
        float x = (threadIdx.x < nw) ? sred[threadIdx.x] : -1e30f;
        #pragma unroll
        for (int o = 16; o; o >>= 1) x = fmaxf(x, __shfl_xor_sync(0xffffffffu, x, o));
        if (threadIdx.x == 0) sred[0] = x;
    }
    __syncthreads();
    float r = sred[0];
    __syncthreads();
    return r;
}

__device__ __forceinline__ float block_reduce_sum(float v, float* sred) {
    #pragma unroll
    for (int o = 16; o; o >>= 1) v += __shfl_xor_sync(0xffffffffu, v, o);
    int w = threadIdx.x >> 5;
    if ((threadIdx.x & 31) == 0) sred[w] = v;
    __syncthreads();
    int nw = (blockDim.x + 31) >> 5;
    if (threadIdx.x < 32) {
        float x = (threadIdx.x < nw) ? sred[threadIdx.x] : 0.f;
        #pragma unroll
        for (int o = 16; o; o >>= 1) x += __shfl_xor_sync(0xffffffffu, x, o);
        if (threadIdx.x == 0) sred[0] = x;
    }
    __syncthreads();
    float r = sred[0];
    __syncthreads();
    return r;
}

__device__ __forceinline__ float warp_reduce_sum(float v) {
    #pragma unroll
    for (int o = 16; o; o >>= 1) v += __shfl_down_sync(0xffffffffu, v, o);
    return v;
}

__device__ __forceinline__ uint32_t smem_u32(const void* p) {
    return (uint32_t)__cvta_generic_to_shared(p);
}
__device__ __forceinline__ void ldsm_x4(uint32_t* r, uint32_t addr) {
    asm volatile("ldmatrix.sync.aligned.m8n8.x4.shared.b16 {%0,%1,%2,%3}, [%4];"
        : "=r"(r[0]), "=r"(r[1]), "=r"(r[2]), "=r"(r[3]) : "r"(addr));
}
__device__ __forceinline__ void mma_bf16(float* d, const uint32_t* a, uint32_t b0, uint32_t b1) {
    asm volatile("mma.sync.aligned.m16n8k16.row.col.f32.bf16.bf16.f32 "
        "{%0,%1,%2,%3}, {%4,%5,%6,%7}, {%8,%9}, {%0,%1,%2,%3};"
        : "+f"(d[0]), "+f"(d[1]), "+f"(d[2]), "+f"(d[3])
        : "r"(a[0]), "r"(a[1]), "r"(a[2]), "r"(a[3]), "r"(b0), "r"(b1));
}
__device__ __forceinline__ float trunc_hi(float x) {
    return __uint_as_float(__float_as_uint(x) & 0xffff0000u);
}
__device__ __forceinline__ uint4 pack_hi8(float4 a, float4 b) {
    __nv_bfloat162 p0 = __floats2bfloat162_rn(trunc_hi(a.x), trunc_hi(a.y));
    __nv_bfloat162 p1 = __floats2bfloat162_rn(trunc_hi(a.z), trunc_hi(a.w));
    __nv_bfloat162 p2 = __floats2bfloat162_rn(trunc_hi(b.x), trunc_hi(b.y));
    __nv_bfloat162 p3 = __floats2bfloat162_rn(trunc_hi(b.z), trunc_hi(b.w));
    uint4 r;
    r.x = *(uint32_t*)&p0; r.y = *(uint32_t*)&p1;
    r.z = *(uint32_t*)&p2; r.w = *(uint32_t*)&p3;
    return r;
}
__device__ __forceinline__ uint4 pack_lo8(float4 a, float4 b) {
    __nv_bfloat162 p0 = __floats2bfloat162_rn(a.x - trunc_hi(a.x), a.y - trunc_hi(a.y));
    __nv_bfloat162 p1 = __floats2bfloat162_rn(a.z - trunc_hi(a.z), a.w - trunc_hi(a.w));
    __nv_bfloat162 p2 = __floats2bfloat162_rn(b.x - trunc_hi(b.x), b.y - trunc_hi(b.y));
    __nv_bfloat162 p3 = __floats2bfloat162_rn(b.z - trunc_hi(b.z), b.w - trunc_hi(b.w));
    uint4 r;
    r.x = *(uint32_t*)&p0; r.y = *(uint32_t*)&p1;
    r.z = *(uint32_t*)&p2; r.w = *(uint32_t*)&p3;
    return r;
}

// ---------------- kernels ----------------

__global__ void k_init() {
    int i = blockIdx.x * blockDim.x + threadIdx.x;
    if (i < H) g_attn_applied[i] = 0.f;
    if (i < L) g_score_c[i] = 0.f;
}

// attn logit half-dots: 2 warps/row, plain stores (no atomics, no bias)
__global__ void k_attn_logits(const int* __restrict__ din_p,
                              const float* __restrict__ emb,
                              const float* __restrict__ h0,
                              const float* __restrict__ Ww) {
    int g    = (blockIdx.x * blockDim.x + threadIdx.x) >> 5;
    int lane = threadIdx.x & 31;
    if (g >= 2 * ML) return;
    int row = g >> 1;
    int seg = g & 1;
    const float4* w4 = (const float4*)(Ww + (size_t)row * (2 * H) + seg * H);
    const float4* x4 = seg ? (const float4*)h0
                           : (const float4*)(emb + (size_t)din_p[0] * H);
    float acc = 0.f;
    #pragma unroll
    for (int q = lane; q < 256; q += 32) {
        float4 a = w4[q]; float4 x = x4[q];
        acc += a.x * x.x + a.y * x.y + a.z * x.z + a.w * x.w;
    }
    acc = warp_reduce_sum(acc);
    if (lane == 0) g_al2[seg * ML + row] = acc;
}

// fused softmax(ML) + attn_applied; E rows prefetched BEFORE the reduction
__global__ void k_attn_applied(const float* __restrict__ E, const float* __restrict__ bw) {
    __shared__ float sred[32];
    __shared__ float w[16];
    int t = threadIdx.x;
    int r0 = blockIdx.x * 16;
    float ev[16];
    #pragma unroll
    for (int i = 0; i < 16; i++)
        ev[i] = E[(size_t)(r0 + i) * H + t];
    float a = g_al2[t]        + g_al2[ML + t]        + bw[t];
    float b = g_al2[t + 1024] + g_al2[ML + t + 1024] + bw[t + 1024];
    float m = block_reduce_max(fmaxf(a, b), sred);
    float s = block_reduce_sum(expf(a - m) + expf(b - m), sred);
    float inv = 1.f / s;
    if (t < 16) {
        float lg = g_al2[r0 + t] + g_al2[ML + r0 + t] + bw[r0 + t];
        w[t] = expf(lg - m) * inv;
    }
    __syncthreads();
    float acc = 0.f;
    #pragma unroll
    for (int i = 0; i < 16; i++)
        acc += w[i] * ev[i];
    atomicAdd(&g_attn_applied[t], acc);
}

// rnn_in[j] = relu([emb0, attn_applied] . W_attn_u[j] + b_attn_u[j])
__global__ void k_rnn_in(const int* __restrict__ din_p,
                         const float* __restrict__ emb,
                         const float* __restrict__ Wu,
                         const float* __restrict__ bu) {
    int row  = (blockIdx.x * blockDim.x + threadIdx.x) >> 5;
    int lane = threadIdx.x & 31;
    if (row >= H) return;
    const float4* w4 = (const float4*)(Wu + (size_t)row * (2 * H));
    const float4* e4 = (const float4*)(emb + (size_t)din_p[0] * H);
    const float4* a4 = (const float4*)g_attn_applied;
    float acc = 0.f;
    #pragma unroll
    for (int q = lane; q < 256; q += 32) {
        float4 a = w4[q]; float4 x = e4[q];
        acc += a.x * x.x + a.y * x.y + a.z * x.z + a.w * x.w;
    }
    #pragma unroll
    for (int q = lane; q < 256; q += 32) {
        float4 a = w4[256 + q]; float4 x = a4[q];
        acc += a.x * x.x + a.y * x.y + a.z * x.z + a.w * x.w;
    }
    acc = warp_reduce_sum(acc);
    if (lane == 0) g_rnn_in[row] = fmaxf(acc + bu[row], 0.f);
}

// gh = W_hh @ h0 + b_hh  (forked early)
__global__ void k_gh(const float* __restrict__ Whh, const float* __restrict__ bhh,
                     const float* __restrict__ h0) {
    int g    = (blockIdx.x * blockDim.x + threadIdx.x) >> 5;
    int lane = threadIdx.x & 31;
    if (g >= 3 * H) return;
    const float4* w4 = (const float4*)(Whh + (size_t)g * H);
    const float4* x4 = (const float4*)h0;
    float acc = 0.f;
    #pragma unroll
    for (int q = lane; q < 256; q += 32) {
        float4 a = w4[q]; float4 x = x4[q];
        acc += a.x * x.x + a.y * x.y + a.z * x.z + a.w * x.w;
    }
    acc = warp_reduce_sum(acc);
    if (lane == 0) g_gh[g] = acc + bhh[g];
}

// gi half-dots: 2 warps/row, plain stores (bias added in k_gru)
__global__ void k_gi(const float* __restrict__ Wih) {
    int g    = (blockIdx.x * blockDim.x + threadIdx.x) >> 5;
    int lane = threadIdx.x & 31;
    if (g >= 2 * 3 * H) return;
    int row = g >> 1;
    int seg = g & 1;
    const float4* w4 = (const float4*)(Wih + (size_t)row * H + seg * (H / 2));
    const float4* x4 = (const float4*)(g_rnn_in + seg * (H / 2));
    float acc = 0.f;
    #pragma unroll
    for (int q = lane; q < 128; q += 32) {
        float4 a = w4[q]; float4 x = x4[q];
        acc += a.x * x.x + a.y * x.y + a.z * x.z + a.w * x.w;
    }
    acc = warp_reduce_sum(acc);
    if (lane == 0) g_gi2[seg][row] = acc;
}

// GRU combine; adds gi halves + bias; writes h_new and final_hidden
__global__ void k_gru(const float* __restrict__ h0, const float* __restrict__ bih,
                      float* __restrict__ out) {
    int t = threadIdx.x;
    float gi0 = g_gi2[0][t]         + g_gi2[1][t]         + bih[t];
    float gi1 = g_gi2[0][H + t]     + g_gi2[1][H + t]     + bih[H + t];
    float gi2 = g_gi2[0][2 * H + t] + g_gi2[1][2 * H + t] + bih[2 * H + t];
    float r = 1.f / (1.f + expf(-(gi0 + g_gh[t])));
    float z = 1.f / (1.f + expf(-(gi1 + g_gh[H + t])));
    float n = tanhf(gi2 + r * g_gh[2 * H + t]);
    float h = (1.f - z) * n + z * h0[t];
    g_hnew[t] = h;
    out[V + t] = h;
}

// score_g[v] = h_new . W_gen[v] + b_gen[v]  — warp per row
__global__ void k_score_g(const float* __restrict__ Wg, const float* __restrict__ bg) {
    int row  = (blockIdx.x * blockDim.x + threadIdx.x) >> 5;
    int lane = threadIdx.x & 31;
    if (row >= V) return;
    const float4* w4 = (const float4*)(Wg + (size_t)row * H);
    const float4* h4 = (const float4*)g_hnew;
    float acc = 0.f;
    #pragma unroll
    for (int q = lane; q < 256; q += 32) {
        float4 a = w4[q]; float4 x = h4[q];
        acc += a.x * x.x + a.y * x.y + a.z * x.z + a.w * x.w;
    }
    acc = warp_reduce_sum(acc);
    if (lane == 0) g_score_g[row] = acc + bg[row];
}

// score_c via split-bf16 tensor-core GEMM, 512 threads (16 warps, 4/SMSP),
// CTA tile 128x128, warp tile 32x32, term-major MMA, fused tanh*h0 epilogue.
#define SAB 40
__global__ __launch_bounds__(512) void k_score_c_mma(
    const float* __restrict__ A,     // E: 2048 x 1024 fp32
    const float* __restrict__ B,     // W_copy: 1024 x 1024 fp32
    const float* __restrict__ bias, const float* __restrict__ h0) {
    __shared__ __nv_bfloat16 sAh[128 * SAB], sAl[128 * SAB];
    __shared__ __nv_bfloat16 sBh[128 * SAB], sBl[128 * SAB];
    int tid  = threadIdx.x;
    int lane = tid & 31;
    int wid  = tid >> 5;           // 0..15
    int wm   = wid >> 2;           // 0..3 (32-row band)
    int wn   = wid & 3;            // 0..3 (32-col band)
    int rowBase = blockIdx.y * 128;
    int colBase = blockIdx.x * 128;

    float acc[2][4][4];
    #pragma unroll
    for (int mf = 0; mf < 2; mf++)
        #pragma unroll
        for (int nf = 0; nf < 4; nf++)
            #pragma unroll
            for (int r = 0; r < 4; r++) acc[mf][nf][r] = 0.f;

    // loader: thread -> (row 0..127, 8-col segment 0..3)
    int lrow = tid >> 2;
    int lseg = tid & 3;
    const float4* A4 = (const float4*)A;   // row stride 256 float4
    const float4* B4 = (const float4*)B;

    float4 fa[2], fb[2];
    #pragma unroll
    for (int q = 0; q < 2; q++) {
        fa[q] = A4[(size_t)(rowBase + lrow) * 256 + lseg * 2 + q];
        fb[q] = B4[(size_t)(colBase + lrow) * 256 + lseg * 2 + q];
    }

    for (int kt = 0; kt < 1024; kt += 32) {
        {
            int c = lseg * 8;
            *(uint4*)&sAh[lrow * SAB + c] = pack_hi8(fa[0], fa[1]);
            *(uint4*)&sAl[lrow * SAB + c] = pack_lo8(fa[0], fa[1]);
            *(uint4*)&sBh[lrow * SAB + c] = pack_hi8(fb[0], fb[1]);
            *(uint4*)&sBl[lrow * SAB + c] = pack_lo8(fb[0], fb[1]);
        }
        __syncthreads();
        if (kt + 32 < 1024) {
            int kq = (kt + 32) >> 2;
            #pragma unroll
            for (int q = 0; q < 2; q++) {
                fa[q] = A4[(size_t)(rowBase + lrow) * 256 + kq + lseg * 2 + q];
                fb[q] = B4[(size_t)(colBase + lrow) * 256 + kq + lseg * 2 + q];
            }
        }
        #pragma unroll
        for (int ks = 0; ks < 2; ks++) {
            int kk = ks * 16;
            uint32_t ah[2][4], al[2][4];
            int arow = wm * 32 + (lane & 15);
            int akc  = kk + ((lane >> 4) & 1) * 8;
            #pragma unroll
            for (int mf = 0; mf < 2; mf++) {
                ldsm_x4(ah[mf], smem_u32(&sAh[(arow + mf * 16) * SAB + akc]));
                ldsm_x4(al[mf], smem_u32(&sAl[(arow + mf * 16) * SAB + akc]));
            }
            uint32_t bh0[4], bh1[4], bl0[4], bl1[4];
            int brow = wn * 32 + lane;
            ldsm_x4(bh0, smem_u32(&sBh[brow * SAB + kk]));
            ldsm_x4(bh1, smem_u32(&sBh[brow * SAB + kk + 8]));
            ldsm_x4(bl0, smem_u32(&sBl[brow * SAB + kk]));
            ldsm_x4(bl1, smem_u32(&sBl[brow * SAB + kk + 8]));
            #pragma unroll
            for (int mf = 0; mf < 2; mf++)
                #pragma unroll
                for (int nf = 0; nf < 4; nf++)
                    mma_bf16(acc[mf][nf], ah[mf], bh0[nf], bh1[nf]);
            #pragma unroll
            for (int mf = 0; mf < 2; mf++)
                #pragma unroll
                for (int nf = 0; nf < 4; nf++)
                    mma_bf16(acc[mf][nf], ah[mf], bl0[nf], bl1[nf]);
            #pragma unroll
            for (int mf = 0; mf < 2; mf++)
                #pragma unroll
                for (int nf = 0; nf < 4; nf++)
                    mma_bf16(acc[mf][nf], al[mf], bh0[nf], bh1[nf]);
        }
        __syncthreads();
    }

    // epilogue: tanh + h0-weighted reduce; rows shared by the 4 wn warps -> atomicAdd
    int g   = lane >> 2;
    int tig = lane & 3;
    float bj[4][2], hj[4][2];
    #pragma unroll
    for (int nf = 0; nf < 4; nf++) {
        int j0 = colBase + wn * 32 + nf * 8 + tig * 2;
        bj[nf][0] = bias[j0];     bj[nf][1] = bias[j0 + 1];
        hj[nf][0] = h0[j0];       hj[nf][1] = h0[j0 + 1];
    }
    #pragma unroll
    for (int mf = 0; mf < 2; mf++) {
        float s0 = 0.f, s1 = 0.f;
        #pragma unroll
        for (int nf = 0; nf < 4; nf++) {
            s0 += tanhf(acc[mf][nf][0] + bj[nf][0]) * hj[nf][0]
                + tanhf(acc[mf][nf][1] + bj[nf][1]) * hj[nf][1];
            s1 += tanhf(acc[mf][nf][2] + bj[nf][0]) * hj[nf][0]
                + tanhf(acc[mf][nf][3] + bj[nf][1]) * hj[nf][1];
        }
        s0 += __shfl_xor_sync(0xffffffffu, s0, 1);
        s0 += __shfl_xor_sync(0xffffffffu, s0, 2);
        s1 += __shfl_xor_sync(0xffffffffu, s1, 1);
        s1 += __shfl_xor_sync(0xffffffffu, s1, 2);
        if (tig == 0) {
            int r = rowBase + wm * 32 + mf * 16 + g;
            atomicAdd(&g_score_c[r], s0);
            atomicAdd(&g_score_c[r + 8], s1);
        }
    }
}

// single-pass per-block (max, local expsum) over concat(score_g, score_c)
__global__ void k_redpass() {
    __shared__ float sred[32];
    int x = blockIdx.x * blockDim.x + threadIdx.x;
    float v = -1e30f;
    bool valid = (x < V + L);
    if (valid) v = (x < V) ? g_score_g[x] : g_score_c[x - V];
    float m = block_reduce_max(v, sred);
    float s = valid ? expf(v - m) : 0.f;
    s = block_reduce_sum(s, sred);
    if (threadIdx.x == 0) { g_bmax[blockIdx.x] = m; g_bsum[blockIdx.x] = s; }
}

__global__ void k_redfin() {
    __shared__ float sm[64], ss[64];
    int t = threadIdx.x;
    float m = (t < NRED) ? g_bmax[t] : -1e30f;
    sm[t] = m;
    __syncthreads();
    for (int o = 32; o; o >>= 1) { if (t < o) sm[t] = fmaxf(sm[t], sm[t + o]); __syncthreads(); }
    float M = sm[0];
    float s = (t < NRED) ? g_bsum[t] * expf(g_bmax[t] - M) : 0.f;
    ss[t] = s;
    __syncthreads();
    for (int o = 32; o; o >>= 1) { if (t < o) ss[t] += ss[t + o]; __syncthreads(); }
    if (t == 0) { g_smax = M; g_sinv = 1.f / ss[0]; }
}

// final_output[v] = prob_g[v]; zero final_weights region
__global__ void k_out_g(float* __restrict__ out) {
    int i = blockIdx.x * blockDim.x + threadIdx.x;
    if (i < H) out[V + H + i] = 0.f;
    if (i >= V) return;
    out[i] = expf(g_score_g[i] - g_smax) * g_sinv;
}

// prob_c scatter-add; matched rows directly into final_weights
__global__ void k_out_c(const int* __restrict__ iv, const int* __restrict__ din_p,
                        const float* __restrict__ E, float* __restrict__ out) {
    int i = blockIdx.x * blockDim.x + threadIdx.x;
    if (i >= L) return;
    float pc = expf(g_score_c[i] - g_smax) * g_sinv;
    int id = iv[i];
    atomicAdd(&out[id], pc);
    if (id == din_p[0]) {
        const float* Er = E + (size_t)i * H;
        float* fw = out + V + H;
        for (int j = 0; j < H; j++) atomicAdd(&fw[j], pc * Er[j]);
    }
}

// ---------------- launcher ----------------
extern "C" void kernel_launch(void* const* d_in, const int* in_sizes, int n_in,
                              void* d_out, int out_size) {
    const int*   din  = (const int*)d_in[0];
    const float* h0   = (const float*)d_in[1];
    const float* E    = (const float*)d_in[2];
    const int*   iv   = (const int*)d_in[3];
    const float* emb  = (const float*)d_in[4];
    const float* Ww   = (const float*)d_in[5];
    const float* bw   = (const float*)d_in[6];
    const float* Wu   = (const float*)d_in[7];
    const float* bu   = (const float*)d_in[8];
    const float* Wih  = (const float*)d_in[9];
    const float* bih  = (const float*)d_in[10];
    const float* Whh  = (const float*)d_in[11];
    const float* bhh  = (const float*)d_in[12];
    const float* Wc   = (const float*)d_in[13];
    const float* bc   = (const float*)d_in[14];
    const float* Wg   = (const float*)d_in[15];
    const float* bg   = (const float*)d_in[16];
    float* out = (float*)d_out;

    static cudaStream_t s2 = nullptr, s3 = nullptr;
    static cudaEvent_t evF0 = nullptr, evF1 = nullptr, evGh = nullptr, evJoin = nullptr;
    if (s2 == nullptr) {
        cudaStreamCreateWithFlags(&s2, cudaStreamNonBlocking);
        cudaStreamCreateWithFlags(&s3, cudaStreamNonBlocking);
        cudaEventCreateWithFlags(&evF0, cudaEventDisableTiming);
        cudaEventCreateWithFlags(&evF1, cudaEventDisableTiming);
        cudaEventCreateWithFlags(&evGh, cudaEventDisableTiming);
        cudaEventCreateWithFlags(&evJoin, cudaEventDisableTiming);
    }

    // fork gh (input-only deps) onto s3 immediately
    cudaEventRecord(evF0, 0);
    cudaStreamWaitEvent(s3, evF0, 0);
    k_gh<<<(3 * H * 32) / 256, 256, 0, s3>>>(Whh, bhh, h0);
    cudaEventRecord(evGh, s3);

    k_init<<<8, 256>>>();

    // fork score_c MMA onto s2 (after init: epilogue atomicAdds to g_score_c)
    cudaEventRecord(evF1, 0);
    cudaStreamWaitEvent(s2, evF1, 0);
    {
        dim3 grid(H / 128, L / 128);  // (8, 16)
        k_score_c_mma<<<grid, 512, 0, s2>>>(E, Wc, bc, h0);
    }
    cudaEventRecord(evJoin, s2);

    // main chain
    k_attn_logits<<<(2 * ML * 32) / 256, 256>>>(din, emb, h0, Ww);
    k_attn_applied<<<128, 1024>>>(E, bw);
    k_rnn_in<<<(H * 32) / 256, 256>>>(din, emb, Wu, bu);
    k_gi<<<(2 * 3 * H * 32) / 256, 256>>>(Wih);
    cudaStreamWaitEvent(0, evGh, 0);
    k_gru<<<1, 1024>>>(h0, bih, out);
    k_score_g<<<(V + 7) / 8, 256>>>(Wg, bg);

    // join + tail
    cudaStreamWaitEvent(0, evJoin, 0);
    k_redpass<<<NRED, 1024>>>();
    k_redfin<<<1, 64>>>();
    k_out_g<<<(V + 255) / 256, 256>>>(out);
    k_out_c<<<L / 256, 256>>>(iv, din, E, out);
}

// round 14
// speedup vs baseline: 1.0007x; 1.0007x over previous
#include <cuda_runtime.h>
#include <cuda_bf16.h>
#include <math.h>
#include <stdint.h>

#define V  50257
#define H  1024
#define L  2048
#define ML 2048
#define NRED 52

// ---------------- scratch (device globals; no allocations allowed) ----------------
__device__ float g_al2[2 * ML];      // attn logit half-dots (plain stores, no bias)
__device__ float g_attn_applied[H];
__device__ float g_rnn_in[H];
__device__ float g_gi2[2][3 * H];    // gi half-dots (plain stores, no bias)
__device__ float g_gh[3 * H];
__device__ float g_hnew[H];
__device__ float g_score_g[V];
__device__ float g_score_c[L];
__device__ float g_bmax[NRED];
__device__ float g_bsum[NRED];
__device__ float g_smax;
__device__ float g_sinv;

// ---------------- helpers ----------------
__device__ __forceinline__ float block_reduce_max(float v, float* sred) {
    #pragma unroll
    for (int o = 16; o; o >>= 1) v = fmaxf(v, __shfl_xor_sync(0xffffffffu, v, o));
    int w = threadIdx.x >> 5;
    if ((threadIdx.x & 31) == 0) sred[w] = v;
    __syncthreads();
    int nw = (blockDim.x + 31) >> 5;
    if (threadIdx.x < 32) {
        float x = (threadIdx.x < nw) ? sred[threadIdx.x] : -1e30f;
        #pragma unroll
        for (int o = 16; o; o >>= 1) x = fmaxf(x, __shfl_xor_sync(0xffffffffu, x, o));
        if (threadIdx.x == 0) sred[0] = x;
    }
    __syncthreads();
    float r = sred[0];
    __syncthreads();
    return r;
}

__device__ __forceinline__ float block_reduce_sum(float v, float* sred) {
    #pragma unroll
    for (int o = 16; o; o >>= 1) v += __shfl_xor_sync(0xffffffffu, v, o);
    int w = threadIdx.x >> 5;
    if ((threadIdx.x & 31) == 0) sred[w] = v;
    __syncthreads();
    int nw = (blockDim.x + 31) >> 5;
    if (threadIdx.x < 32) {
        float x = (threadIdx.x < nw) ? sred[threadIdx.x] : 0.f;
        #pragma unroll
        for (int o = 16; o; o >>= 1) x += __shfl_xor_sync(0xffffffffu, x, o);
        if (threadIdx.x == 0) sred[0] = x;
    }
    __syncthreads();
    float r = sred[0];
    __syncthreads();
    return r;
}

__device__ __forceinline__ float warp_reduce_sum(float v) {
    #pragma unroll
    for (int o = 16; o; o >>= 1) v += __shfl_down_sync(0xffffffffu, v, o);
    return v;
}

__device__ __forceinline__ uint32_t smem_u32(const void* p) {
    return (uint32_t)__cvta_generic_to_shared(p);
}
__device__ __forceinline__ void ldsm_x4(uint32_t* r, uint32_t addr) {
    asm volatile("ldmatrix.sync.aligned.m8n8.x4.shared.b16 {%0,%1,%2,%3}, [%4];"
        : "=r"(r[0]), "=r"(r[1]), "=r"(r[2]), "=r"(r[3]) : "r"(addr));
}
__device__ __forceinline__ void mma_bf16(float* d, const uint32_t* a, uint32_t b0, uint32_t b1) {
    asm volatile("mma.sync.aligned.m16n8k16.row.col.f32.bf16.bf16.f32 "
        "{%0,%1,%2,%3}, {%4,%5,%6,%7}, {%8,%9}, {%0,%1,%2,%3};"
        : "+f"(d[0]), "+f"(d[1]), "+f"(d[2]), "+f"(d[3])
        : "r"(a[0]), "r"(a[1]), "r"(a[2]), "r"(a[3]), "r"(b0), "r"(b1));
}
__device__ __forceinline__ float trunc_hi(float x) {
    return __uint_as_float(__float_as_uint(x) & 0xffff0000u);
}
__device__ __forceinline__ uint4 pack_hi8(float4 a, float4 b) {
    __nv_bfloat162 p0 = __floats2bfloat162_rn(trunc_hi(a.x), trunc_hi(a.y));
    __nv_bfloat162 p1 = __floats2bfloat162_rn(trunc_hi(a.z), trunc_hi(a.w));
    __nv_bfloat162 p2 = __floats2bfloat162_rn(trunc_hi(b.x), trunc_hi(b.y));
    __nv_bfloat162 p3 = __floats2bfloat162_rn(trunc_hi(b.z), trunc_hi(b.w));
    uint4 r;
    r.x = *(uint32_t*)&p0; r.y = *(uint32_t*)&p1;
    r.z = *(uint32_t*)&p2; r.w = *(uint32_t*)&p3;
    return r;
}
__device__ __forceinline__ uint4 pack_lo8(float4 a, float4 b) {
    __nv_bfloat162 p0 = __floats2bfloat162_rn(a.x - trunc_hi(a.x), a.y - trunc_hi(a.y));
    __nv_bfloat162 p1 = __floats2bfloat162_rn(a.z - trunc_hi(a.z), a.w - trunc_hi(a.w));
    __nv_bfloat162 p2 = __floats2bfloat162_rn(b.x - trunc_hi(b.x), b.y - trunc_hi(b.y));
    __nv_bfloat162 p3 = __floats2bfloat162_rn(b.z - trunc_hi(b.z), b.w - trunc_hi(b.w));
    uint4 r;
    r.x = *(uint32_t*)&p0; r.y = *(uint32_t*)&p1;
    r.z = *(uint32_t*)&p2; r.w = *(uint32_t*)&p3;
    return r;
}
__device__ __forceinline__ float4 ldcs4(const float4* p) {
    return __ldcs(p);
}

// ---------------- kernels ----------------

__global__ void k_init() {
    int i = blockIdx.x * blockDim.x + threadIdx.x;
    if (i < H) g_attn_applied[i] = 0.f;
    if (i < L) g_score_c[i] = 0.f;
}

// attn logit half-dots: 2 warps/row, plain stores (no atomics, no bias)
__global__ void k_attn_logits(const int* __restrict__ din_p,
                              const float* __restrict__ emb,
                              const float* __restrict__ h0,
                              const float* __restrict__ Ww) {
    int g    = (blockIdx.x * blockDim.x + threadIdx.x) >> 5;
    int lane = threadIdx.x & 31;
    if (g >= 2 * ML) return;
    int row = g >> 1;
    int seg = g & 1;
    const float4* w4 = (const float4*)(Ww + (size_t)row * (2 * H) + seg * H);
    const float4* x4 = seg ? (const float4*)h0
                           : (const float4*)(emb + (size_t)din_p[0] * H);
    float acc = 0.f;
    #pragma unroll
    for (int q = lane; q < 256; q += 32) {
        float4 a = ldcs4(&w4[q]); float4 x = x4[q];
        acc += a.x * x.x + a.y * x.y + a.z * x.z + a.w * x.w;
    }
    acc = warp_reduce_sum(acc);
    if (lane == 0) g_al2[seg * ML + row] = acc;
}

// fused softmax(ML) + attn_applied; E rows prefetched BEFORE the reduction
__global__ void k_attn_applied(const float* __restrict__ E, const float* __restrict__ bw) {
    __shared__ float sred[32];
    __shared__ float w[16];
    int t = threadIdx.x;
    int r0 = blockIdx.x * 16;
    float ev[16];
    #pragma unroll
    for (int i = 0; i < 16; i++)
        ev[i] = E[(size_t)(r0 + i) * H + t];
    float a = g_al2[t]        + g_al2[ML + t]        + bw[t];
    float b = g_al2[t + 1024] + g_al2[ML + t + 1024] + bw[t + 1024];
    float m = block_reduce_max(fmaxf(a, b), sred);
    float s = block_reduce_sum(expf(a - m) + expf(b - m), sred);
    float inv = 1.f / s;
    if (t < 16) {
        float lg = g_al2[r0 + t] + g_al2[ML + r0 + t] + bw[r0 + t];
        w[t] = expf(lg - m) * inv;
    }
    __syncthreads();
    float acc = 0.f;
    #pragma unroll
    for (int i = 0; i < 16; i++)
        acc += w[i] * ev[i];
    atomicAdd(&g_attn_applied[t], acc);
}

// rnn_in[j] = relu([emb0, attn_applied] . W_attn_u[j] + b_attn_u[j])
__global__ void k_rnn_in(const int* __restrict__ din_p,
                         const float* __restrict__ emb,
                         const float* __restrict__ Wu,
                         const float* __restrict__ bu) {
    int row  = (blockIdx.x * blockDim.x + threadIdx.x) >> 5;
    int lane = threadIdx.x & 31;
    if (row >= H) return;
    const float4* w4 = (const float4*)(Wu + (size_t)row * (2 * H));
    const float4* e4 = (const float4*)(emb + (size_t)din_p[0] * H);
    const float4* a4 = (const float4*)g_attn_applied;
    float acc = 0.f;
    #pragma unroll
    for (int q = lane; q < 256; q += 32) {
        float4 a = ldcs4(&w4[q]); float4 x = e4[q];
        acc += a.x * x.x + a.y * x.y + a.z * x.z + a.w * x.w;
    }
    #pragma unroll
    for (int q = lane; q < 256; q += 32) {
        float4 a = ldcs4(&w4[256 + q]); float4 x = a4[q];
        acc += a.x * x.x + a.y * x.y + a.z * x.z + a.w * x.w;
    }
    acc = warp_reduce_sum(acc);
    if (lane == 0) g_rnn_in[row] = fmaxf(acc + bu[row], 0.f);
}

// gh = W_hh @ h0 + b_hh  (forked early)
__global__ void k_gh(const float* __restrict__ Whh, const float* __restrict__ bhh,
                     const float* __restrict__ h0) {
    int g    = (blockIdx.x * blockDim.x + threadIdx.x) >> 5;
    int lane = threadIdx.x & 31;
    if (g >= 3 * H) return;
    const float4* w4 = (const float4*)(Whh + (size_t)g * H);
    const float4* x4 = (const float4*)h0;
    float acc = 0.f;
    #pragma unroll
    for (int q = lane; q < 256; q += 32) {
        float4 a = ldcs4(&w4[q]); float4 x = x4[q];
        acc += a.x * x.x + a.y * x.y + a.z * x.z + a.w * x.w;
    }
    acc = warp_reduce_sum(acc);
    if (lane == 0) g_gh[g] = acc + bhh[g];
}

// gi half-dots: 2 warps/row, plain stores (bias added in k_gru)
__global__ void k_gi(const float* __restrict__ Wih) {
    int g    = (blockIdx.x * blockDim.x + threadIdx.x) >> 5;
    int lane = threadIdx.x & 31;
    if (g >= 2 * 3 * H) return;
    int row = g >> 1;
    int seg = g & 1;
    const float4* w4 = (const float4*)(Wih + (size_t)row * H + seg * (H / 2));
    const float4* x4 = (const float4*)(g_rnn_in + seg * (H / 2));
    float acc = 0.f;
    #pragma unroll
    for (int q = lane; q < 128; q += 32) {
        float4 a = ldcs4(&w4[q]); float4 x = x4[q];
        acc += a.x * x.x + a.y * x.y + a.z * x.z + a.w * x.w;
    }
    acc = warp_reduce_sum(acc);
    if (lane == 0) g_gi2[seg][row] = acc;
}

// GRU combine; adds gi halves + bias; writes h_new and final_hidden
__global__ void k_gru(const float* __restrict__ h0, const float* __restrict__ bih,
                      float* __restrict__ out) {
    int t = threadIdx.x;
    float gi0 = g_gi2[0][t]         + g_gi2[1][t]         + bih[t];
    float gi1 = g_gi2[0][H + t]     + g_gi2[1][H + t]     + bih[H + t];
    float gi2 = g_gi2[0][2 * H + t] + g_gi2[1][2 * H + t] + bih[2 * H + t];
    float r = 1.f / (1.f + expf(-(gi0 + g_gh[t])));
    float z = 1.f / (1.f + expf(-(gi1 + g_gh[H + t])));
    float n = tanhf(gi2 + r * g_gh[2 * H + t]);
    float h = (1.f - z) * n + z * h0[t];
    g_hnew[t] = h;
    out[V + t] = h;
}

// score_g[v] = h_new . W_gen[v] + b_gen[v]  — warp per row, streaming loads
__global__ void k_score_g(const float* __restrict__ Wg, const float* __restrict__ bg) {
    int row  = (blockIdx.x * blockDim.x + threadIdx.x) >> 5;
    int lane = threadIdx.x & 31;
    if (row >= V) return;
    const float4* w4 = (const float4*)(Wg + (size_t)row * H);
    const float4* h4 = (const float4*)g_hnew;
    float acc = 0.f;
    #pragma unroll
    for (int q = lane; q < 256; q += 32) {
        float4 a = ldcs4(&w4[q]); float4 x = h4[q];
        acc += a.x * x.x + a.y * x.y + a.z * x.z + a.w * x.w;
    }
    acc = warp_reduce_sum(acc);
    if (lane == 0) g_score_g[row] = acc + bg[row];
}

// score_c via split-bf16 tensor-core GEMM with in-kernel fp32->hi/lo conversion.
// CTA 128x128, K-tile 32, 8 warps (2x4), warp tile 64x32, m16n8k16.
// ALL fragments for the kt tile (both ks halves) loaded before the 96 MMAs.
#define SAB 40
__global__ __launch_bounds__(256) void k_score_c_mma(
    const float* __restrict__ A,     // E: 2048 x 1024 fp32
    const float* __restrict__ B,     // W_copy: 1024 x 1024 fp32
    const float* __restrict__ bias, const float* __restrict__ h0) {
    __shared__ __nv_bfloat16 sAh[128 * SAB], sAl[128 * SAB];
    __shared__ __nv_bfloat16 sBh[128 * SAB], sBl[128 * SAB];
    int tid  = threadIdx.x;
    int lane = tid & 31;
    int wid  = tid >> 5;
    int wm   = wid >> 2;
    int wn   = wid & 3;
    int rowBase = blockIdx.y * 128;
    int colBase = blockIdx.x * 128;

    float acc[4][4][4];
    #pragma unroll
    for (int mf = 0; mf < 4; mf++)
        #pragma unroll
        for (int nf = 0; nf < 4; nf++)
            #pragma unroll
            for (int r = 0; r < 4; r++) acc[mf][nf][r] = 0.f;

    int lrow  = tid >> 1;
    int lhalf = tid & 1;
    const float4* A4 = (const float4*)A;
    const float4* B4 = (const float4*)B;

    float4 fa[4], fb[4];
    #pragma unroll
    for (int q = 0; q < 4; q++) {
        fa[q] = ldcs4(&A4[(size_t)(rowBase + lrow) * 256 + lhalf * 4 + q]);
        fb[q] = ldcs4(&B4[(size_t)(colBase + lrow) * 256 + lhalf * 4 + q]);
    }

    for (int kt = 0; kt < 1024; kt += 32) {
        {
            int c = lhalf * 16;
            *(uint4*)&sAh[lrow * SAB + c]     = pack_hi8(fa[0], fa[1]);
            *(uint4*)&sAh[lrow * SAB + c + 8] = pack_hi8(fa[2], fa[3]);
            *(uint4*)&sAl[lrow * SAB + c]     = pack_lo8(fa[0], fa[1]);
            *(uint4*)&sAl[lrow * SAB + c + 8] = pack_lo8(fa[2], fa[3]);
            *(uint4*)&sBh[lrow * SAB + c]     = pack_hi8(fb[0], fb[1]);
            *(uint4*)&sBh[lrow * SAB + c + 8] = pack_hi8(fb[2], fb[3]);
            *(uint4*)&sBl[lrow * SAB + c]     = pack_lo8(fb[0], fb[1]);
            *(uint4*)&sBl[lrow * SAB + c + 8] = pack_lo8(fb[2], fb[3]);
        }
        __syncthreads();
        if (kt + 32 < 1024) {
            int kq = (kt + 32) >> 2;
            #pragma unroll
            for (int q = 0; q < 4; q++) {
                fa[q] = ldcs4(&A4[(size_t)(rowBase + lrow) * 256 + kq + lhalf * 4 + q]);
                fb[q] = ldcs4(&B4[(size_t)(colBase + lrow) * 256 + kq + lhalf * 4 + q]);
            }
        }
        // ---- hoisted fragment loads for BOTH ks halves ----
        uint32_t ah[2][4][4], al[2][4][4];
        uint32_t bh0[2][4], bh1[2][4], bl0[2][4], bl1[2][4];
        int arow = wm * 64 + (lane & 15);
        int brow = wn * 32 + lane;
        #pragma unroll
        for (int ks = 0; ks < 2; ks++) {
            int kk = ks * 16;
            int akc = kk + ((lane >> 4) & 1) * 8;
            #pragma unroll
            for (int mf = 0; mf < 4; mf++) {
                ldsm_x4(ah[ks][mf], smem_u32(&sAh[(arow + mf * 16) * SAB + akc]));
                ldsm_x4(al[ks][mf], smem_u32(&sAl[(arow + mf * 16) * SAB + akc]));
            }
            ldsm_x4(bh0[ks], smem_u32(&sBh[brow * SAB + kk]));
            ldsm_x4(bh1[ks], smem_u32(&sBh[brow * SAB + kk + 8]));
            ldsm_x4(bl0[ks], smem_u32(&sBl[brow * SAB + kk]));
            ldsm_x4(bl1[ks], smem_u32(&sBl[brow * SAB + kk + 8]));
        }
        // ---- 96 MMAs, term-major ----
        #pragma unroll
        for (int ks = 0; ks < 2; ks++)
            #pragma unroll
            for (int mf = 0; mf < 4; mf++)
                #pragma unroll
                for (int nf = 0; nf < 4; nf++)
                    mma_bf16(acc[mf][nf], ah[ks][mf], bh0[ks][nf], bh1[ks][nf]);
        #pragma unroll
        for (int ks = 0; ks < 2; ks++)
            #pragma unroll
            for (int mf = 0; mf < 4; mf++)
                #pragma unroll
                for (int nf = 0; nf < 4; nf++)
                    mma_bf16(acc[mf][nf], ah[ks][mf], bl0[ks][nf], bl1[ks][nf]);
        #pragma unroll
        for (int ks = 0; ks < 2; ks++)
            #pragma unroll
            for (int mf = 0; mf < 4; mf++)
                #pragma unroll
                for (int nf = 0; nf < 4; nf++)
                    mma_bf16(acc[mf][nf], al[ks][mf], bh0[ks][nf], bh1[ks][nf]);
        __syncthreads();
    }

    // epilogue: tanh + h0-weighted reduce over j; per-row atomicAdd
    int g   = lane >> 2;
    int tig = lane & 3;
    float bj[4][2], hj[4][2];
    #pragma unroll
    for (int nf = 0; nf < 4; nf++) {
        int j0 = colBase + wn * 32 + nf * 8 + tig * 2;
        bj[nf][0] = bias[j0];     bj[nf][1] = bias[j0 + 1];
        hj[nf][0] = h0[j0];       hj[nf][1] = h0[j0 + 1];
    }
    #pragma unroll
    for (int mf = 0; mf < 4; mf++) {
        float s0 = 0.f, s1 = 0.f;
        #pragma unroll
        for (int nf = 0; nf < 4; nf++) {
            s0 += tanhf(acc[mf][nf][0] + bj[nf][0]) * hj[nf][0]
                + tanhf(acc[mf][nf][1] + bj[nf][1]) * hj[nf][1];
            s1 += tanhf(acc[mf][nf][2] + bj[nf][0]) * hj[nf][0]
                + tanhf(acc[mf][nf][3] + bj[nf][1]) * hj[nf][1];
        }
        s0 += __shfl_xor_sync(0xffffffffu, s0, 1);
        s0 += __shfl_xor_sync(0xffffffffu, s0, 2);
        s1 += __shfl_xor_sync(0xffffffffu, s1, 1);
        s1 += __shfl_xor_sync(0xffffffffu, s1, 2);
        if (tig == 0) {
            int r = rowBase + wm * 64 + mf * 16 + g;
            atomicAdd(&g_score_c[r], s0);
            atomicAdd(&g_score_c[r + 8], s1);
        }
    }
}

// single-pass per-block (max, local expsum) over concat(score_g, score_c)
__global__ void k_redpass() {
    __shared__ float sred[32];
    int x = blockIdx.x * blockDim.x + threadIdx.x;
    float v = -1e30f;
    bool valid = (x < V + L);
    if (valid) v = (x < V) ? g_score_g[x] : g_score_c[x - V];
    float m = block_reduce_max(v, sred);
    float s = valid ? expf(v - m) : 0.f;
    s = block_reduce_sum(s, sred);
    if (threadIdx.x == 0) { g_bmax[blockIdx.x] = m; g_bsum[blockIdx.x] = s; }
}

__global__ void k_redfin() {
    __shared__ float sm[64], ss[64];
    int t = threadIdx.x;
    float m = (t < NRED) ? g_bmax[t] : -1e30f;
    sm[t] = m;
    __syncthreads();
    for (int o = 32; o; o >>= 1) { if (t < o) sm[t] = fmaxf(sm[t], sm[t + o]); __syncthreads(); }
    float M = sm[0];
    float s = (t < NRED) ? g_bsum[t] * expf(g_bmax[t] - M) : 0.f;
    ss[t] = s;
    __syncthreads();
    for (int o = 32; o; o >>= 1) { if (t < o) ss[t] += ss[t + o]; __syncthreads(); }
    if (t == 0) { g_smax = M; g_sinv = 1.f / ss[0]; }
}

// final_output[v] = prob_g[v]; zero final_weights region
__global__ void k_out_g(float* __restrict__ out) {
    int i = blockIdx.x * blockDim.x + threadIdx.x;
    if (i < H) out[V + H + i] = 0.f;
    if (i >= V) return;
    out[i] = expf(g_score_g[i] - g_smax) * g_sinv;
}

// prob_c scatter-add; matched rows directly into final_weights
__global__ void k_out_c(const int* __restrict__ iv, const int* __restrict__ din_p,
                        const float* __restrict__ E, float* __restrict__ out) {
    int i = blockIdx.x * blockDim.x + threadIdx.x;
    if (i >= L) return;
    float pc = expf(g_score_c[i] - g_smax) * g_sinv;
    int id = iv[i];
    atomicAdd(&out[id], pc);
    if (id == din_p[0]) {
        const float* Er = E + (size_t)i * H;
        float* fw = out + V + H;
        for (int j = 0; j < H; j++) atomicAdd(&fw[j], pc * Er[j]);
    }
}

// ---------------- launcher ----------------
extern "C" void kernel_launch(void* const* d_in, const int* in_sizes, int n_in,
                              void* d_out, int out_size) {
    const int*   din  = (const int*)d_in[0];
    const float* h0   = (const float*)d_in[1];
    const float* E    = (const float*)d_in[2];
    const int*   iv   = (const int*)d_in[3];
    const float* emb  = (const float*)d_in[4];
    const float* Ww   = (const float*)d_in[5];
    const float* bw   = (const float*)d_in[6];
    const float* Wu   = (const float*)d_in[7];
    const float* bu   = (const float*)d_in[8];
    const float* Wih  = (const float*)d_in[9];
    const float* bih  = (const float*)d_in[10];
    const float* Whh  = (const float*)d_in[11];
    const float* bhh  = (const float*)d_in[12];
    const float* Wc   = (const float*)d_in[13];
    const float* bc   = (const float*)d_in[14];
    const float* Wg   = (const float*)d_in[15];
    const float* bg   = (const float*)d_in[16];
    float* out = (float*)d_out;

    static cudaStream_t s2 = nullptr, s3 = nullptr;
    static cudaEvent_t evF0 = nullptr, evF1 = nullptr, evGh = nullptr, evJoin = nullptr;
    if (s2 == nullptr) {
        cudaStreamCreateWithFlags(&s2, cudaStreamNonBlocking);
        cudaStreamCreateWithFlags(&s3, cudaStreamNonBlocking);
        cudaEventCreateWithFlags(&evF0, cudaEventDisableTiming);
        cudaEventCreateWithFlags(&evF1, cudaEventDisableTiming);
        cudaEventCreateWithFlags(&evGh, cudaEventDisableTiming);
        cudaEventCreateWithFlags(&evJoin, cudaEventDisableTiming);
    }

    // fork gh (input-only deps) onto s3 immediately
    cudaEventRecord(evF0, 0);
    cudaStreamWaitEvent(s3, evF0, 0);
    k_gh<<<(3 * H * 32) / 256, 256, 0, s3>>>(Whh, bhh, h0);
    cudaEventRecord(evGh, s3);

    k_init<<<8, 256>>>();

    // fork score_c MMA onto s2 (after init: epilogue atomicAdds to g_score_c)
    cudaEventRecord(evF1, 0);
    cudaStreamWaitEvent(s2, evF1, 0);
    {
        dim3 grid(H / 128, L / 128);  // (8, 16)
        k_score_c_mma<<<grid, 256, 0, s2>>>(E, Wc, bc, h0);
    }
    cudaEventRecord(evJoin, s2);

    // main chain
    k_attn_logits<<<(2 * ML * 32) / 256, 256>>>(din, emb, h0, Ww);
    k_attn_applied<<<128, 1024>>>(E, bw);
    k_rnn_in<<<(H * 32) / 256, 256>>>(din, emb, Wu, bu);
    k_gi<<<(2 * 3 * H * 32) / 256, 256>>>(Wih);
    cudaStreamWaitEvent(0, evGh, 0);
    k_gru<<<1, 1024>>>(h0, bih, out);
    k_score_g<<<(V + 7) / 8, 256>>>(Wg, bg);

    // join + tail
    cudaStreamWaitEvent(0, evJoin, 0);
    k_redpass<<<NRED, 1024>>>();
    k_redfin<<<1, 64>>>();
    k_out_g<<<(V + 255) / 256, 256>>>(out);
    k_out_c<<<L / 256, 256>>>(iv, din, E, out);
}

// round 15
// speedup vs baseline: 1.0982x; 1.0975x over previous
#include <cuda_runtime.h>
#include <cuda_bf16.h>
#include <math.h>
#include <stdint.h>

#define V  50257
#define H  1024
#define L  2048
#define ML 2048
#define NRED 52

// ---------------- scratch (device globals; no allocations allowed) ----------------
__device__ float g_al2[2 * ML];      // attn logit half-dots (plain stores, no bias)
__device__ float g_attn_applied[H];
__device__ float g_rnn_in[H];
__device__ float g_gi2[2][3 * H];    // gi half-dots (plain stores, no bias)
__device__ float g_gh[3 * H];
__device__ float g_hnew[H];
__device__ float g_score_g[V];
__device__ float g_score_c[L];
__device__ float g_bmax[NRED];
__device__ float g_bsum[NRED];
__device__ float g_smax;
__device__ float g_sinv;

// ---------------- helpers ----------------
__device__ __forceinline__ float block_reduce_max(float v, float* sred) {
    #pragma unroll
    for (int o = 16; o; o >>= 1) v = fmaxf(v, __shfl_xor_sync(0xffffffffu, v, o));
    int w = threadIdx.x >> 5;
    if ((threadIdx.x & 31) == 0) sred[w] = v;
    __syncthreads();
    int nw = (blockDim.x + 31) >> 5;
    if (threadIdx.x < 32) {
        float x = (threadIdx.x < nw) ? sred[threadIdx.x] : -1e30f;
        #pragma unroll
        for (int o = 16; o; o >>= 1) x = fmaxf(x, __shfl_xor_sync(0xffffffffu, x, o));
        if (threadIdx.x == 0) sred[0] = x;
    }
    __syncthreads();
    float r = sred[0];
    __syncthreads();
    return r;
}

__device__ __forceinline__ float block_reduce_sum(float v, float* sred) {
    #pragma unroll
    for (int o = 16; o; o >>= 1) v += __shfl_xor_sync(0xffffffffu, v, o);
    int w = threadIdx.x >> 5;
    if ((threadIdx.x & 31) == 0) sred[w] = v;
    __syncthreads();
    int nw = (blockDim.x + 31) >> 5;
    if (threadIdx.x < 32) {
        float x = (threadIdx.x < nw) ? sred[threadIdx.x] : 0.f;
        #pragma unroll
        for (int o = 16; o; o >>= 1) x += __shfl_xor_sync(0xffffffffu, x, o);
        if (threadIdx.x == 0) sred[0] = x;
    }
    __syncthreads();
    float r = sred[0];
    __syncthreads();
    return r;
}

__device__ __forceinline__ float warp_reduce_sum(float v) {
    #pragma unroll
    for (int o = 16; o; o >>= 1) v += __shfl_down_sync(0xffffffffu, v, o);
    return v;
}

__device__ __forceinline__ uint32_t smem_u32(const void* p) {
    return (uint32_t)__cvta_generic_to_shared(p);
}
__device__ __forceinline__ void ldsm_x4(uint32_t* r, uint32_t addr) {
    asm volatile("ldmatrix.sync.aligned.m8n8.x4.shared.b16 {%0,%1,%2,%3}, [%4];"
        : "=r"(r[0]), "=r"(r[1]), "=r"(r[2]), "=r"(r[3]) : "r"(addr));
}
__device__ __forceinline__ void mma_bf16(float* d, const uint32_t* a, uint32_t b0, uint32_t b1) {
    asm volatile("mma.sync.aligned.m16n8k16.row.col.f32.bf16.bf16.f32 "
        "{%0,%1,%2,%3}, {%4,%5,%6,%7}, {%8,%9}, {%0,%1,%2,%3};"
        : "+f"(d[0]), "+f"(d[1]), "+f"(d[2]), "+f"(d[3])
        : "r"(a[0]), "r"(a[1]), "r"(a[2]), "r"(a[3]), "r"(b0), "r"(b1));
}
__device__ __forceinline__ float trunc_hi(float x) {
    return __uint_as_float(__float_as_uint(x) & 0xffff0000u);
}
__device__ __forceinline__ uint4 pack_hi8(float4 a, float4 b) {
    __nv_bfloat162 p0 = __floats2bfloat162_rn(trunc_hi(a.x), trunc_hi(a.y));
    __nv_bfloat162 p1 = __floats2bfloat162_rn(trunc_hi(a.z), trunc_hi(a.w));
    __nv_bfloat162 p2 = __floats2bfloat162_rn(trunc_hi(b.x), trunc_hi(b.y));
    __nv_bfloat162 p3 = __floats2bfloat162_rn(trunc_hi(b.z), trunc_hi(b.w));
    uint4 r;
    r.x = *(uint32_t*)&p0; r.y = *(uint32_t*)&p1;
    r.z = *(uint32_t*)&p2; r.w = *(uint32_t*)&p3;
    return r;
}
__device__ __forceinline__ uint4 pack_lo8(float4 a, float4 b) {
    __nv_bfloat162 p0 = __floats2bfloat162_rn(a.x - trunc_hi(a.x), a.y - trunc_hi(a.y));
    __nv_bfloat162 p1 = __floats2bfloat162_rn(a.z - trunc_hi(a.z), a.w - trunc_hi(a.w));
    __nv_bfloat162 p2 = __floats2bfloat162_rn(b.x - trunc_hi(b.x), b.y - trunc_hi(b.y));
    __nv_bfloat162 p3 = __floats2bfloat162_rn(b.z - trunc_hi(b.z), b.w - trunc_hi(b.w));
    uint4 r;
    r.x = *(uint32_t*)&p0; r.y = *(uint32_t*)&p1;
    r.z = *(uint32_t*)&p2; r.w = *(uint32_t*)&p3;
    return r;
}
__device__ __forceinline__ float4 ldcs4(const float4* p) {
    return __ldcs(p);
}

// ---------------- kernels ----------------

__global__ void k_init() {
    int i = blockIdx.x * blockDim.x + threadIdx.x;
    if (i < H) g_attn_applied[i] = 0.f;
    if (i < L) g_score_c[i] = 0.f;
}

// attn logit half-dots: 2 warps/row, plain stores (no atomics, no bias)
__global__ void k_attn_logits(const int* __restrict__ din_p,
                              const float* __restrict__ emb,
                              const float* __restrict__ h0,
                              const float* __restrict__ Ww) {
    int g    = (blockIdx.x * blockDim.x + threadIdx.x) >> 5;
    int lane = threadIdx.x & 31;
    if (g >= 2 * ML) return;
    int row = g >> 1;
    int seg = g & 1;
    const float4* w4 = (const float4*)(Ww + (size_t)row * (2 * H) + seg * H);
    const float4* x4 = seg ? (const float4*)h0
                           : (const float4*)(emb + (size_t)din_p[0] * H);
    float acc = 0.f;
    #pragma unroll
    for (int q = lane; q < 256; q += 32) {
        float4 a = ldcs4(&w4[q]); float4 x = x4[q];
        acc += a.x * x.x + a.y * x.y + a.z * x.z + a.w * x.w;
    }
    acc = warp_reduce_sum(acc);
    if (lane == 0) g_al2[seg * ML + row] = acc;
}

// fused softmax(ML) + attn_applied; E rows prefetched BEFORE the reduction
__global__ void k_attn_applied(const float* __restrict__ E, const float* __restrict__ bw) {
    __shared__ float sred[32];
    __shared__ float w[16];
    int t = threadIdx.x;
    int r0 = blockIdx.x * 16;
    float ev[16];
    #pragma unroll
    for (int i = 0; i < 16; i++)
        ev[i] = E[(size_t)(r0 + i) * H + t];
    float a = g_al2[t]        + g_al2[ML + t]        + bw[t];
    float b = g_al2[t + 1024] + g_al2[ML + t + 1024] + bw[t + 1024];
    float m = block_reduce_max(fmaxf(a, b), sred);
    float s = block_reduce_sum(expf(a - m) + expf(b - m), sred);
    float inv = 1.f / s;
    if (t < 16) {
        float lg = g_al2[r0 + t] + g_al2[ML + r0 + t] + bw[r0 + t];
        w[t] = expf(lg - m) * inv;
    }
    __syncthreads();
    float acc = 0.f;
    #pragma unroll
    for (int i = 0; i < 16; i++)
        acc += w[i] * ev[i];
    atomicAdd(&g_attn_applied[t], acc);
}

// rnn_in[j] = relu([emb0, attn_applied] . W_attn_u[j] + b_attn_u[j])
__global__ void k_rnn_in(const int* __restrict__ din_p,
                         const float* __restrict__ emb,
                         const float* __restrict__ Wu,
                         const float* __restrict__ bu) {
    int row  = (blockIdx.x * blockDim.x + threadIdx.x) >> 5;
    int lane = threadIdx.x & 31;
    if (row >= H) return;
    const float4* w4 = (const float4*)(Wu + (size_t)row * (2 * H));
    const float4* e4 = (const float4*)(emb + (size_t)din_p[0] * H);
    const float4* a4 = (const float4*)g_attn_applied;
    float acc = 0.f;
    #pragma unroll
    for (int q = lane; q < 256; q += 32) {
        float4 a = ldcs4(&w4[q]); float4 x = e4[q];
        acc += a.x * x.x + a.y * x.y + a.z * x.z + a.w * x.w;
    }
    #pragma unroll
    for (int q = lane; q < 256; q += 32) {
        float4 a = ldcs4(&w4[256 + q]); float4 x = a4[q];
        acc += a.x * x.x + a.y * x.y + a.z * x.z + a.w * x.w;
    }
    acc = warp_reduce_sum(acc);
    if (lane == 0) g_rnn_in[row] = fmaxf(acc + bu[row], 0.f);
}

// gh = W_hh @ h0 + b_hh  (forked early)
__global__ void k_gh(const float* __restrict__ Whh, const float* __restrict__ bhh,
                     const float* __restrict__ h0) {
    int g    = (blockIdx.x * blockDim.x + threadIdx.x) >> 5;
    int lane = threadIdx.x & 31;
    if (g >= 3 * H) return;
    const float4* w4 = (const float4*)(Whh + (size_t)g * H);
    const float4* x4 = (const float4*)h0;
    float acc = 0.f;
    #pragma unroll
    for (int q = lane; q < 256; q += 32) {
        float4 a = ldcs4(&w4[q]); float4 x = x4[q];
        acc += a.x * x.x + a.y * x.y + a.z * x.z + a.w * x.w;
    }
    acc = warp_reduce_sum(acc);
    if (lane == 0) g_gh[g] = acc + bhh[g];
}

// gi half-dots: 2 warps/row, plain stores (bias added in k_gru)
__global__ void k_gi(const float* __restrict__ Wih) {
    int g    = (blockIdx.x * blockDim.x + threadIdx.x) >> 5;
    int lane = threadIdx.x & 31;
    if (g >= 2 * 3 * H) return;
    int row = g >> 1;
    int seg = g & 1;
    const float4* w4 = (const float4*)(Wih + (size_t)row * H + seg * (H / 2));
    const float4* x4 = (const float4*)(g_rnn_in + seg * (H / 2));
    float acc = 0.f;
    #pragma unroll
    for (int q = lane; q < 128; q += 32) {
        float4 a = ldcs4(&w4[q]); float4 x = x4[q];
        acc += a.x * x.x + a.y * x.y + a.z * x.z + a.w * x.w;
    }
    acc = warp_reduce_sum(acc);
    if (lane == 0) g_gi2[seg][row] = acc;
}

// GRU combine; adds gi halves + bias; writes h_new and final_hidden
__global__ void k_gru(const float* __restrict__ h0, const float* __restrict__ bih,
                      float* __restrict__ out) {
    int t = threadIdx.x;
    float gi0 = g_gi2[0][t]         + g_gi2[1][t]         + bih[t];
    float gi1 = g_gi2[0][H + t]     + g_gi2[1][H + t]     + bih[H + t];
    float gi2 = g_gi2[0][2 * H + t] + g_gi2[1][2 * H + t] + bih[2 * H + t];
    float r = 1.f / (1.f + expf(-(gi0 + g_gh[t])));
    float z = 1.f / (1.f + expf(-(gi1 + g_gh[H + t])));
    float n = tanhf(gi2 + r * g_gh[2 * H + t]);
    float h = (1.f - z) * n + z * h0[t];
    g_hnew[t] = h;
    out[V + t] = h;
}

// score_g: 4 rows per warp with interleaved loads — 4x in-flight bytes per lane,
// so the 206MB stream saturates HBM even at reduced warp occupancy under the MMA.
__global__ void k_score_g(const float* __restrict__ Wg, const float* __restrict__ bg) {
    int gw   = (blockIdx.x * blockDim.x + threadIdx.x) >> 5;
    int lane = threadIdx.x & 31;
    int row0 = gw * 4;
    if (row0 >= V) return;
    const float4* h4 = (const float4*)g_hnew;
    if (row0 + 4 <= V) {
        const float4* w0 = (const float4*)(Wg + (size_t)(row0 + 0) * H);
        const float4* w1 = (const float4*)(Wg + (size_t)(row0 + 1) * H);
        const float4* w2 = (const float4*)(Wg + (size_t)(row0 + 2) * H);
        const float4* w3 = (const float4*)(Wg + (size_t)(row0 + 3) * H);
        float a0 = 0.f, a1 = 0.f, a2 = 0.f, a3 = 0.f;
        #pragma unroll
        for (int q = lane; q < 256; q += 32) {
            float4 v0 = ldcs4(&w0[q]);
            float4 v1 = ldcs4(&w1[q]);
            float4 v2 = ldcs4(&w2[q]);
            float4 v3 = ldcs4(&w3[q]);
            float4 x  = h4[q];
            a0 += v0.x * x.x + v0.y * x.y + v0.z * x.z + v0.w * x.w;
            a1 += v1.x * x.x + v1.y * x.y + v1.z * x.z + v1.w * x.w;
            a2 += v2.x * x.x + v2.y * x.y + v2.z * x.z + v2.w * x.w;
            a3 += v3.x * x.x + v3.y * x.y + v3.z * x.z + v3.w * x.w;
        }
        a0 = warp_reduce_sum(a0);
        a1 = warp_reduce_sum(a1);
        a2 = warp_reduce_sum(a2);
        a3 = warp_reduce_sum(a3);
        if (lane == 0) {
            g_score_g[row0 + 0] = a0 + bg[row0 + 0];
            g_score_g[row0 + 1] = a1 + bg[row0 + 1];
            g_score_g[row0 + 2] = a2 + bg[row0 + 2];
            g_score_g[row0 + 3] = a3 + bg[row0 + 3];
        }
    } else {
        for (int r = 0; r < 4 && row0 + r < V; r++) {
            const float4* w4 = (const float4*)(Wg + (size_t)(row0 + r) * H);
            float acc = 0.f;
            #pragma unroll
            for (int q = lane; q < 256; q += 32) {
                float4 a = ldcs4(&w4[q]); float4 x = h4[q];
                acc += a.x * x.x + a.y * x.y + a.z * x.z + a.w * x.w;
            }
            acc = warp_reduce_sum(acc);
            if (lane == 0) g_score_g[row0 + r] = acc + bg[row0 + r];
        }
    }
}

// score_c via split-bf16 tensor-core GEMM (R14 exact)
#define SAB 40
__global__ __launch_bounds__(256) void k_score_c_mma(
    const float* __restrict__ A,     // E: 2048 x 1024 fp32
    const float* __restrict__ B,     // W_copy: 1024 x 1024 fp32
    const float* __restrict__ bias, const float* __restrict__ h0) {
    __shared__ __nv_bfloat16 sAh[128 * SAB], sAl[128 * SAB];
    __shared__ __nv_bfloat16 sBh[128 * SAB], sBl[128 * SAB];
    int tid  = threadIdx.x;
    int lane = tid & 31;
    int wid  = tid >> 5;
    int wm   = wid >> 2;
    int wn   = wid & 3;
    int rowBase = blockIdx.y * 128;
    int colBase = blockIdx.x * 128;

    float acc[4][4][4];
    #pragma unroll
    for (int mf = 0; mf < 4; mf++)
        #pragma unroll
        for (int nf = 0; nf < 4; nf++)
            #pragma unroll
            for (int r = 0; r < 4; r++) acc[mf][nf][r] = 0.f;

    int lrow  = tid >> 1;
    int lhalf = tid & 1;
    const float4* A4 = (const float4*)A;
    const float4* B4 = (const float4*)B;

    float4 fa[4], fb[4];
    #pragma unroll
    for (int q = 0; q < 4; q++) {
        fa[q] = ldcs4(&A4[(size_t)(rowBase + lrow) * 256 + lhalf * 4 + q]);
        fb[q] = ldcs4(&B4[(size_t)(colBase + lrow) * 256 + lhalf * 4 + q]);
    }

    for (int kt = 0; kt < 1024; kt += 32) {
        {
            int c = lhalf * 16;
            *(uint4*)&sAh[lrow * SAB + c]     = pack_hi8(fa[0], fa[1]);
            *(uint4*)&sAh[lrow * SAB + c + 8] = pack_hi8(fa[2], fa[3]);
            *(uint4*)&sAl[lrow * SAB + c]     = pack_lo8(fa[0], fa[1]);
            *(uint4*)&sAl[lrow * SAB + c + 8] = pack_lo8(fa[2], fa[3]);
            *(uint4*)&sBh[lrow * SAB + c]     = pack_hi8(fb[0], fb[1]);
            *(uint4*)&sBh[lrow * SAB + c + 8] = pack_hi8(fb[2], fb[3]);
            *(uint4*)&sBl[lrow * SAB + c]     = pack_lo8(fb[0], fb[1]);
            *(uint4*)&sBl[lrow * SAB + c + 8] = pack_lo8(fb[2], fb[3]);
        }
        __syncthreads();
        if (kt + 32 < 1024) {
            int kq = (kt + 32) >> 2;
            #pragma unroll
            for (int q = 0; q < 4; q++) {
                fa[q] = ldcs4(&A4[(size_t)(rowBase + lrow) * 256 + kq + lhalf * 4 + q]);
                fb[q] = ldcs4(&B4[(size_t)(colBase + lrow) * 256 + kq + lhalf * 4 + q]);
            }
        }
        uint32_t ah[2][4][4], al[2][4][4];
        uint32_t bh0[2][4], bh1[2][4], bl0[2][4], bl1[2][4];
        int arow = wm * 64 + (lane & 15);
        int brow = wn * 32 + lane;
        #pragma unroll
        for (int ks = 0; ks < 2; ks++) {
            int kk = ks * 16;
            int akc = kk + ((lane >> 4) & 1) * 8;
            #pragma unroll
            for (int mf = 0; mf < 4; mf++) {
                ldsm_x4(ah[ks][mf], smem_u32(&sAh[(arow + mf * 16) * SAB + akc]));
                ldsm_x4(al[ks][mf], smem_u32(&sAl[(arow + mf * 16) * SAB + akc]));
            }
            ldsm_x4(bh0[ks], smem_u32(&sBh[brow * SAB + kk]));
            ldsm_x4(bh1[ks], smem_u32(&sBh[brow * SAB + kk + 8]));
            ldsm_x4(bl0[ks], smem_u32(&sBl[brow * SAB + kk]));
            ldsm_x4(bl1[ks], smem_u32(&sBl[brow * SAB + kk + 8]));
        }
        #pragma unroll
        for (int ks = 0; ks < 2; ks++)
            #pragma unroll
            for (int mf = 0; mf < 4; mf++)
                #pragma unroll
                for (int nf = 0; nf < 4; nf++)
                    mma_bf16(acc[mf][nf], ah[ks][mf], bh0[ks][nf], bh1[ks][nf]);
        #pragma unroll
        for (int ks = 0; ks < 2; ks++)
            #pragma unroll
            for (int mf = 0; mf < 4; mf++)
                #pragma unroll
                for (int nf = 0; nf < 4; nf++)
                    mma_bf16(acc[mf][nf], ah[ks][mf], bl0[ks][nf], bl1[ks][nf]);
        #pragma unroll
        for (int ks = 0; ks < 2; ks++)
            #pragma unroll
            for (int mf = 0; mf < 4; mf++)
                #pragma unroll
                for (int nf = 0; nf < 4; nf++)
                    mma_bf16(acc[mf][nf], al[ks][mf], bh0[ks][nf], bh1[ks][nf]);
        __syncthreads();
    }

    int g   = lane >> 2;
    int tig = lane & 3;
    float bj[4][2], hj[4][2];
    #pragma unroll
    for (int nf = 0; nf < 4; nf++) {
        int j0 = colBase + wn * 32 + nf * 8 + tig * 2;
        bj[nf][0] = bias[j0];     bj[nf][1] = bias[j0 + 1];
        hj[nf][0] = h0[j0];       hj[nf][1] = h0[j0 + 1];
    }
    #pragma unroll
    for (int mf = 0; mf < 4; mf++) {
        float s0 = 0.f, s1 = 0.f;
        #pragma unroll
        for (int nf = 0; nf < 4; nf++) {
            s0 += tanhf(acc[mf][nf][0] + bj[nf][0]) * hj[nf][0]
                + tanhf(acc[mf][nf][1] + bj[nf][1]) * hj[nf][1];
            s1 += tanhf(acc[mf][nf][2] + bj[nf][0]) * hj[nf][0]
                + tanhf(acc[mf][nf][3] + bj[nf][1]) * hj[nf][1];
        }
        s0 += __shfl_xor_sync(0xffffffffu, s0, 1);
        s0 += __shfl_xor_sync(0xffffffffu, s0, 2);
        s1 += __shfl_xor_sync(0xffffffffu, s1, 1);
        s1 += __shfl_xor_sync(0xffffffffu, s1, 2);
        if (tig == 0) {
            int r = rowBase + wm * 64 + mf * 16 + g;
            atomicAdd(&g_score_c[r], s0);
            atomicAdd(&g_score_c[r + 8], s1);
        }
    }
}

// single-pass per-block (max, local expsum) over concat(score_g, score_c)
__global__ void k_redpass() {
    __shared__ float sred[32];
    int x = blockIdx.x * blockDim.x + threadIdx.x;
    float v = -1e30f;
    bool valid = (x < V + L);
    if (valid) v = (x < V) ? g_score_g[x] : g_score_c[x - V];
    float m = block_reduce_max(v, sred);
    float s = valid ? expf(v - m) : 0.f;
    s = block_reduce_sum(s, sred);
    if (threadIdx.x == 0) { g_bmax[blockIdx.x] = m; g_bsum[blockIdx.x] = s; }
}

__global__ void k_redfin() {
    __shared__ float sm[64], ss[64];
    int t = threadIdx.x;
    float m = (t < NRED) ? g_bmax[t] : -1e30f;
    sm[t] = m;
    __syncthreads();
    for (int o = 32; o; o >>= 1) { if (t < o) sm[t] = fmaxf(sm[t], sm[t + o]); __syncthreads(); }
    float M = sm[0];
    float s = (t < NRED) ? g_bsum[t] * expf(g_bmax[t] - M) : 0.f;
    ss[t] = s;
    __syncthreads();
    for (int o = 32; o; o >>= 1) { if (t < o) ss[t] += ss[t + o]; __syncthreads(); }
    if (t == 0) { g_smax = M; g_sinv = 1.f / ss[0]; }
}

// final_output[v] = prob_g[v]; zero final_weights region
__global__ void k_out_g(float* __restrict__ out) {
    int i = blockIdx.x * blockDim.x + threadIdx.x;
    if (i < H) out[V + H + i] = 0.f;
    if (i >= V) return;
    out[i] = expf(g_score_g[i] - g_smax) * g_sinv;
}

// prob_c scatter-add; matched rows directly into final_weights
__global__ void k_out_c(const int* __restrict__ iv, const int* __restrict__ din_p,
                        const float* __restrict__ E, float* __restrict__ out) {
    int i = blockIdx.x * blockDim.x + threadIdx.x;
    if (i >= L) return;
    float pc = expf(g_score_c[i] - g_smax) * g_sinv;
    int id = iv[i];
    atomicAdd(&out[id], pc);
    if (id == din_p[0]) {
        const float* Er = E + (size_t)i * H;
        float* fw = out + V + H;
        for (int j = 0; j < H; j++) atomicAdd(&fw[j], pc * Er[j]);
    }
}

// ---------------- launcher ----------------
extern "C" void kernel_launch(void* const* d_in, const int* in_sizes, int n_in,
                              void* d_out, int out_size) {
    const int*   din  = (const int*)d_in[0];
    const float* h0   = (const float*)d_in[1];
    const float* E    = (const float*)d_in[2];
    const int*   iv   = (const int*)d_in[3];
    const float* emb  = (const float*)d_in[4];
    const float* Ww   = (const float*)d_in[5];
    const float* bw   = (const float*)d_in[6];
    const float* Wu   = (const float*)d_in[7];
    const float* bu   = (const float*)d_in[8];
    const float* Wih  = (const float*)d_in[9];
    const float* bih  = (const float*)d_in[10];
    const float* Whh  = (const float*)d_in[11];
    const float* bhh  = (const float*)d_in[12];
    const float* Wc   = (const float*)d_in[13];
    const float* bc   = (const float*)d_in[14];
    const float* Wg   = (const float*)d_in[15];
    const float* bg   = (const float*)d_in[16];
    float* out = (float*)d_out;

    static cudaStream_t s2 = nullptr, s3 = nullptr;
    static cudaEvent_t evF0 = nullptr, evF1 = nullptr, evGh = nullptr, evJoin = nullptr;
    if (s2 == nullptr) {
        cudaStreamCreateWithFlags(&s2, cudaStreamNonBlocking);
        cudaStreamCreateWithFlags(&s3, cudaStreamNonBlocking);
        cudaEventCreateWithFlags(&evF0, cudaEventDisableTiming);
        cudaEventCreateWithFlags(&evF1, cudaEventDisableTiming);
        cudaEventCreateWithFlags(&evGh, cudaEventDisableTiming);
        cudaEventCreateWithFlags(&evJoin, cudaEventDisableTiming);
    }

    // fork gh (input-only deps) onto s3 immediately
    cudaEventRecord(evF0, 0);
    cudaStreamWaitEvent(s3, evF0, 0);
    k_gh<<<(3 * H * 32) / 256, 256, 0, s3>>>(Whh, bhh, h0);
    cudaEventRecord(evGh, s3);

    k_init<<<8, 256>>>();

    // fork score_c MMA onto s2 (after init: epilogue atomicAdds to g_score_c)
    cudaEventRecord(evF1, 0);
    cudaStreamWaitEvent(s2, evF1, 0);
    {
        dim3 grid(H / 128, L / 128);  // (8, 16)
        k_score_c_mma<<<grid, 256, 0, s2>>>(E, Wc, bc, h0);
    }
    cudaEventRecord(evJoin, s2);

    // main chain
    k_attn_logits<<<(2 * ML * 32) / 256, 256>>>(din, emb, h0, Ww);
    k_attn_applied<<<128, 1024>>>(E, bw);
    k_rnn_in<<<(H * 32) / 256, 256>>>(din, emb, Wu, bu);
    k_gi<<<(2 * 3 * H * 32) / 256, 256>>>(Wih);
    cudaStreamWaitEvent(0, evGh, 0);
    k_gru<<<1, 1024>>>(h0, bih, out);
    {
        int warps = (V + 3) / 4;             // 12565
        int blocks = (warps * 32 + 255) / 256;
        k_score_g<<<blocks, 256>>>(Wg, bg);
    }

    // join + tail
    cudaStreamWaitEvent(0, evJoin, 0);
    k_redpass<<<NRED, 1024>>>();
    k_redfin<<<1, 64>>>();
    k_out_g<<<(V + 255) / 256, 256>>>(out);
    k_out_c<<<L / 256, 256>>>(iv, din, E, out);
}